// round 4
// baseline (speedup 1.0000x reference)
#include <cuda_runtime.h>
#include <cuda_fp16.h>
#include <math.h>

#define BATCH 4
#define CHN 64
#define HW 65536        // 256*256
#define NDS 4096        // 64*64 downsampled pixels
#define THITA_F 1.0e-4f
#define OUT2OFF (BATCH * CHN * HW)

// ---------------- scratch (device globals) ----------------------------------
__device__ float  g_xds[BATCH * CHN * NDS];     // down4(x) fp32 [b][c][n]
__device__ float  g_efd[BATCH * CHN * NDS];     // ef downsampled fp32 [b][c][n]
__device__ __half g_qh[BATCH * NDS * CHN];      // [b][n][d] f16
__device__ __half g_kh[BATCH * NDS * CHN];
__device__ __half g_vh[BATCH * NDS * CHN];
__device__ float  g_O[BATCH * CHN * NDS];       // attention output [b][d][m]

// ============================================================================
// shared small-GEMM helpers (64x64 conv at ds pixels, 4 threads/pixel)
// ============================================================================
__device__ __forceinline__ void gemm64(float* acc, const float* ws,
                                       const float* src, int q, int nn)
{
    #pragma unroll
    for (int c = 0; c < 64; c += 4) {
        float v0 = src[c * 68 + nn],       v1 = src[(c + 1) * 68 + nn];
        float v2 = src[(c + 2) * 68 + nn], v3 = src[(c + 3) * 68 + nn];
        #pragma unroll
        for (int j = 0; j < 16; j++) {
            const float4 w4 = *(const float4*)&ws[(q * 16 + j) * 68 + c];
            acc[j] = fmaf(w4.x, v0, acc[j]);
            acc[j] = fmaf(w4.y, v1, acc[j]);
            acc[j] = fmaf(w4.z, v2, acc[j]);
            acc[j] = fmaf(w4.w, v3, acc[j]);
        }
    }
}
__device__ __forceinline__ void load_ws64(float* ws, const float* w, int t) {
    #pragma unroll
    for (int r = 0; r < 16; r++) {
        int i = r * 256 + t, o = i >> 6, c = i & 63;
        ws[o * 68 + c] = w[i];
    }
}

// ============================================================================
// K1: conv0_ds — x at downsampled pixels only (fp32). 256 thr, 64 px/block.
// ============================================================================
#define C0DS_SMEM (64 * 196 * 4 + 192 * 68 * 4)
__global__ __launch_bounds__(256) void conv0ds_kernel(
    const float* __restrict__ x1, const float* __restrict__ x2,
    const float* __restrict__ w,  const float* __restrict__ bias)
{
    extern __shared__ float sm[];
    float* ws = sm;                 // [64][196]
    float* as = sm + 64 * 196;      // [192][68]
    int t = threadIdx.x, q = t >> 6, nn = t & 63;
    int blk = blockIdx.x, b = blockIdx.y;
    int n = (blk << 6) + nn;

    for (int i = t; i < 12288; i += 256) {
        int o = i / 192, c = i - o * 192;
        ws[o * 196 + c] = w[i];
    }
    for (int i = t; i < 12288; i += 256) {
        int c = i >> 6, x = i & 63;
        const float* s = (c < 128) ? x1 + (size_t)(b * 128 + c) * HW
                                   : x2 + (size_t)(b * 64 + c - 128) * HW;
        as[c * 68 + x] = s[(blk << 10) + (x << 2)];
    }
    __syncthreads();

    float acc[16];
    #pragma unroll
    for (int j = 0; j < 16; j++) acc[j] = 0.0f;
    #pragma unroll
    for (int c = 0; c < 192; c += 4) {
        float v0 = as[c * 68 + nn],       v1 = as[(c + 1) * 68 + nn];
        float v2 = as[(c + 2) * 68 + nn], v3 = as[(c + 3) * 68 + nn];
        #pragma unroll
        for (int j = 0; j < 16; j++) {
            const float4 w4 = *(const float4*)&ws[(q * 16 + j) * 196 + c];
            acc[j] = fmaf(w4.x, v0, acc[j]);
            acc[j] = fmaf(w4.y, v1, acc[j]);
            acc[j] = fmaf(w4.z, v2, acc[j]);
            acc[j] = fmaf(w4.w, v3, acc[j]);
        }
    }
    #pragma unroll
    for (int j = 0; j < 16; j++) {
        int o = q * 16 + j;
        g_xds[(size_t)(b * 64 + o) * NDS + n] =
            fmaxf(acc[j] + __ldg(&bias[o]), 0.0f);
    }
}

// ============================================================================
// K2: ef path at ds pixels (fp32): two chained 64x64 convs.
// ============================================================================
#define EF_SMEM (3 * 64 * 68 * 4)
__global__ __launch_bounds__(256) void ef_kernel(
    const float* __restrict__ event,
    const float* __restrict__ w0, const float* __restrict__ b0,
    const float* __restrict__ w1, const float* __restrict__ b1)
{
    extern __shared__ float sm[];
    float* ws = sm;
    float* ts = sm + 64 * 68;
    float* ae = sm + 2 * 64 * 68;
    int t = threadIdx.x, q = t >> 6, nn = t & 63;
    int blk = blockIdx.x, b = blockIdx.y;
    int n = (blk << 6) + nn;

    load_ws64(ws, w0, t);
    for (int i = t; i < 4096; i += 256) {
        int c = i >> 6, x = i & 63;
        ae[c * 68 + x] = event[(size_t)(b * 64 + c) * HW + (blk << 10) + (x << 2)];
    }
    __syncthreads();

    float acc[16];
    #pragma unroll
    for (int j = 0; j < 16; j++) acc[j] = 0.0f;
    gemm64(acc, ws, ae, q, nn);
    #pragma unroll
    for (int j = 0; j < 16; j++)
        ts[(q * 16 + j) * 68 + nn] = fmaxf(acc[j] + __ldg(&b0[q * 16 + j]), 0.0f);
    __syncthreads();
    load_ws64(ws, w1, t);
    __syncthreads();

    #pragma unroll
    for (int j = 0; j < 16; j++) acc[j] = 0.0f;
    gemm64(acc, ws, ts, q, nn);
    #pragma unroll
    for (int j = 0; j < 16; j++) {
        int o = q * 16 + j;
        g_efd[(size_t)(b * 64 + o) * NDS + n] =
            fmaxf(acc[j] + __ldg(&b1[o]), 0.0f);
    }
}

// ============================================================================
// K3: qkv — t = relu(xw1@x_ds), q/v from t, k from ef_d. f16 [b][n][d] out.
// ============================================================================
#define QKV_SMEM (3 * 64 * 68 * 4)
__device__ __forceinline__ unsigned hpack(__half a, __half b) {
    __half2 h = __halves2half2(a, b);
    return *(unsigned*)&h;
}
__device__ __forceinline__ void store16h(__half* dst, const float* acc,
                                         const float* bias, int o0)
{
    unsigned u[8];
    #pragma unroll
    for (int j = 0; j < 8; j++) {
        float r0 = fmaxf(acc[2*j]   + __ldg(&bias[o0 + 2*j]),   0.0f);
        float r1 = fmaxf(acc[2*j+1] + __ldg(&bias[o0 + 2*j+1]), 0.0f);
        u[j] = hpack(__float2half_rn(r0), __float2half_rn(r1));
    }
    ((uint4*)dst)[0] = make_uint4(u[0], u[1], u[2], u[3]);
    ((uint4*)dst)[1] = make_uint4(u[4], u[5], u[6], u[7]);
}

__global__ __launch_bounds__(256) void qkv_kernel(
    const float* __restrict__ xw1, const float* __restrict__ xb1,
    const float* __restrict__ qw,  const float* __restrict__ qb,
    const float* __restrict__ kw,  const float* __restrict__ kb,
    const float* __restrict__ vw,  const float* __restrict__ vb)
{
    extern __shared__ float sm[];
    float* ws = sm;
    float* ts = sm + 64 * 68;
    float* as = sm + 2 * 64 * 68;
    int t = threadIdx.x, q = t >> 6, nn = t & 63;
    int blk = blockIdx.x, b = blockIdx.y;
    int n = (blk << 6) + nn;
    int o0 = q * 16;

    load_ws64(ws, xw1, t);
    for (int i = t; i < 4096; i += 256) {
        int c = i >> 6, x = i & 63;
        as[c * 68 + x] = g_xds[(size_t)(b * 64 + c) * NDS + (blk << 6) + x];
    }
    __syncthreads();

    float acc[16];
    #pragma unroll
    for (int j = 0; j < 16; j++) acc[j] = 0.0f;
    gemm64(acc, ws, as, q, nn);
    #pragma unroll
    for (int j = 0; j < 16; j++)
        ts[(o0 + j) * 68 + nn] = fmaxf(acc[j] + __ldg(&xb1[o0 + j]), 0.0f);
    __syncthreads();
    load_ws64(ws, qw, t);
    __syncthreads();

    #pragma unroll
    for (int j = 0; j < 16; j++) acc[j] = 0.0f;
    gemm64(acc, ws, ts, q, nn);
    store16h(g_qh + ((size_t)b * NDS + n) * 64 + o0, acc, qb, o0);
    __syncthreads();
    load_ws64(ws, vw, t);
    __syncthreads();

    #pragma unroll
    for (int j = 0; j < 16; j++) acc[j] = 0.0f;
    gemm64(acc, ws, ts, q, nn);
    store16h(g_vh + ((size_t)b * NDS + n) * 64 + o0, acc, vb, o0);
    __syncthreads();
    load_ws64(ws, kw, t);
    for (int i = t; i < 4096; i += 256) {
        int c = i >> 6, x = i & 63;
        as[c * 68 + x] = g_efd[(size_t)(b * 64 + c) * NDS + (blk << 6) + x];
    }
    __syncthreads();

    #pragma unroll
    for (int j = 0; j < 16; j++) acc[j] = 0.0f;
    gemm64(acc, ws, as, q, nn);
    store16h(g_kh + ((size_t)b * NDS + n) * 64 + o0, acc, kb, o0);
}

// ============================================================================
// K4: flash attention, f16 mma. ROUND 4: 128-thr blocks (4 warps), M-tile 64,
// 3 CTAs/SM (reg cap 170). Per-warp work identical to round 3.
// ============================================================================
#define SM_STRIDE 72
#define ATTN_SMEM ((64 * SM_STRIDE + 4 * 64 * SM_STRIDE) * 2)

__device__ __forceinline__ void mma16816(float* d,
    unsigned a0, unsigned a1, unsigned a2, unsigned a3,
    unsigned b0, unsigned b1)
{
    asm volatile(
        "mma.sync.aligned.m16n8k16.row.col.f32.f16.f16.f32 "
        "{%0,%1,%2,%3}, {%4,%5,%6,%7}, {%8,%9}, {%0,%1,%2,%3};\n"
        : "+f"(d[0]), "+f"(d[1]), "+f"(d[2]), "+f"(d[3])
        : "r"(a0), "r"(a1), "r"(a2), "r"(a3), "r"(b0), "r"(b1));
}
__device__ __forceinline__ void ldm4(unsigned* r, unsigned a) {
    asm volatile("ldmatrix.sync.aligned.m8n8.x4.shared.b16 {%0,%1,%2,%3}, [%4];\n"
        : "=r"(r[0]), "=r"(r[1]), "=r"(r[2]), "=r"(r[3]) : "r"(a));
}
__device__ __forceinline__ void ldm4t(unsigned* r, unsigned a) {
    asm volatile("ldmatrix.sync.aligned.m8n8.x4.trans.shared.b16 {%0,%1,%2,%3}, [%4];\n"
        : "=r"(r[0]), "=r"(r[1]), "=r"(r[2]), "=r"(r[3]) : "r"(a));
}
__device__ __forceinline__ void cpasync16(unsigned dst, const void* src) {
    asm volatile("cp.async.cg.shared.global [%0], [%1], 16;\n"
        :: "r"(dst), "l"(src));
}
__device__ __forceinline__ float sexp(float s, float c) {
    float t = fmaf(s, 12102203.16f, c);
    t = fmaxf(t, 0.0f);
    return __int_as_float(__float2int_rn(t));
}
__device__ __forceinline__ unsigned packh2(float a, float b) {
    __half2 h = __floats2half2_rn(a, b);
    return *(unsigned*)&h;
}

__global__ __launch_bounds__(128, 3) void attn_kernel()
{
    extern __shared__ __half smh[];
    __half* qs  = smh;                       // 64 x 72
    __half* ks0 = smh + 64 * SM_STRIDE;      // 2 x 64 x 72
    __half* vs0 = ks0 + 2 * 64 * SM_STRIDE;  // 2 x 64 x 72

    int tid  = threadIdx.x;
    int lane = tid & 31, w = tid >> 5;       // w: 0..3
    int gid  = lane >> 2, tig = lane & 3;
    int b    = blockIdx.y;
    int m0   = blockIdx.x << 6;

    const __half* qg = g_qh + (size_t)b * NDS * 64;
    const __half* kg = g_kh + (size_t)b * NDS * 64;
    const __half* vg = g_vh + (size_t)b * NDS * 64;

    unsigned qs_base = (unsigned)__cvta_generic_to_shared(qs);
    unsigned ks_base = (unsigned)__cvta_generic_to_shared(ks0);
    unsigned vs_base = (unsigned)__cvta_generic_to_shared(vs0);

    #pragma unroll
    for (int rep = 0; rep < 4; rep++) {
        int c = tid + rep * 128;             // 0..511
        int row = c >> 3, off = c & 7;
        cpasync16(ks_base + (row * SM_STRIDE + off * 8) * 2, kg + row * 64 + off * 8);
        cpasync16(vs_base + (row * SM_STRIDE + off * 8) * 2, vg + row * 64 + off * 8);
    }
    asm volatile("cp.async.commit_group;\n");

    for (int c = tid; c < 512; c += 128) {
        int row = c >> 3, off = c & 7;
        *(uint4*)(qs + row * SM_STRIDE + off * 8) =
            *(const uint4*)(qg + (size_t)(m0 + row) * 64 + off * 8);
    }
    asm volatile("cp.async.wait_group 0;\n");
    __syncthreads();

    unsigned qa[4][4];
    {
        int row = (w << 4) + (lane & 15);
        #pragma unroll
        for (int kc = 0; kc < 4; kc++) {
            int dof = kc * 16 + (lane >> 4) * 8;
            ldm4(qa[kc], qs_base + (row * SM_STRIDE + dof) * 2);
        }
    }

    float Of[8][4];
    #pragma unroll
    for (int dc = 0; dc < 8; dc++)
        #pragma unroll
        for (int q = 0; q < 4; q++) Of[dc][q] = 0.0f;
    float mrow0 = -1e30f, mrow1 = -1e30f, lrow0 = 0.0f, lrow1 = 0.0f;
    const unsigned ONES = 0x3C003C00u;

    for (int it = 0; it < 64; it++) {
        int bf = it & 1;
        unsigned ksb = ks_base + bf * 64 * SM_STRIDE * 2;
        unsigned vsb = vs_base + bf * 64 * SM_STRIDE * 2;

        if (it + 1 < 64) {
            int n0n = (it + 1) << 6;
            int nb  = (it + 1) & 1;
            #pragma unroll
            for (int rep = 0; rep < 4; rep++) {
                int c = tid + rep * 128;
                int row = c >> 3, off = c & 7;
                cpasync16(ks_base + (nb * 64 * SM_STRIDE + row * SM_STRIDE + off * 8) * 2,
                          kg + (size_t)(n0n + row) * 64 + off * 8);
                cpasync16(vs_base + (nb * 64 * SM_STRIDE + row * SM_STRIDE + off * 8) * 2,
                          vg + (size_t)(n0n + row) * 64 + off * 8);
            }
            asm volatile("cp.async.commit_group;\n");
        }

        float S[8][4];
        #pragma unroll
        for (int nc = 0; nc < 8; nc++) {
            unsigned kb[8];
            int krow = nc * 8 + (lane & 7);
            int kd   = (lane >> 3) * 8;
            ldm4(kb,     ksb + (krow * SM_STRIDE + kd) * 2);
            ldm4(kb + 4, ksb + (krow * SM_STRIDE + 32 + kd) * 2);
            #pragma unroll
            for (int q = 0; q < 4; q++) S[nc][q] = 0.0f;
            mma16816(S[nc], qa[0][0], qa[0][1], qa[0][2], qa[0][3], kb[0], kb[1]);
            mma16816(S[nc], qa[1][0], qa[1][1], qa[1][2], qa[1][3], kb[2], kb[3]);
            mma16816(S[nc], qa[2][0], qa[2][1], qa[2][2], qa[2][3], kb[4], kb[5]);
            mma16816(S[nc], qa[3][0], qa[3][1], qa[3][2], qa[3][3], kb[6], kb[7]);
        }

        float tm0 = fmaxf(S[0][0], S[0][1]);
        float tm1 = fmaxf(S[0][2], S[0][3]);
        #pragma unroll
        for (int nc = 1; nc < 8; nc++) {
            tm0 = fmaxf(tm0, fmaxf(S[nc][0], S[nc][1]));
            tm1 = fmaxf(tm1, fmaxf(S[nc][2], S[nc][3]));
        }
        tm0 = fmaxf(tm0, __shfl_xor_sync(0xffffffffu, tm0, 1));
        tm0 = fmaxf(tm0, __shfl_xor_sync(0xffffffffu, tm0, 2));
        tm1 = fmaxf(tm1, __shfl_xor_sync(0xffffffffu, tm1, 1));
        tm1 = fmaxf(tm1, __shfl_xor_sync(0xffffffffu, tm1, 2));
        float nm0 = fmaxf(mrow0, tm0), nm1 = fmaxf(mrow1, tm1);
        float sc0 = exp2f((mrow0 - nm0) * 1.44269504f);
        float sc1 = exp2f((mrow1 - nm1) * 1.44269504f);
        mrow0 = nm0; mrow1 = nm1;
        float c0 = 1064866805.0f - nm0 * 12102203.16f;
        float c1 = 1064866805.0f - nm1 * 12102203.16f;

        unsigned P[4][4];
        #pragma unroll
        for (int jc = 0; jc < 4; jc++) {
            P[jc][0] = packh2(sexp(S[2*jc][0],   c0), sexp(S[2*jc][1],   c0));
            P[jc][1] = packh2(sexp(S[2*jc][2],   c1), sexp(S[2*jc][3],   c1));
            P[jc][2] = packh2(sexp(S[2*jc+1][0], c0), sexp(S[2*jc+1][1], c0));
            P[jc][3] = packh2(sexp(S[2*jc+1][2], c1), sexp(S[2*jc+1][3], c1));
        }

        float lf[4] = {0.0f, 0.0f, 0.0f, 0.0f};
        #pragma unroll
        for (int jc = 0; jc < 4; jc++)
            mma16816(lf, P[jc][0], P[jc][1], P[jc][2], P[jc][3], ONES, ONES);
        lrow0 = lrow0 * sc0 + lf[0];
        lrow1 = lrow1 * sc1 + lf[2];

        #pragma unroll
        for (int dc = 0; dc < 8; dc++) {
            Of[dc][0] *= sc0; Of[dc][1] *= sc0;
            Of[dc][2] *= sc1; Of[dc][3] *= sc1;
        }

        #pragma unroll
        for (int jc = 0; jc < 4; jc++) {
            int vrow = jc * 16 + (lane & 15);
            int vcb  = (lane >> 4) * 8;
            #pragma unroll
            for (int dcp = 0; dcp < 4; dcp++) {
                unsigned vb[4];
                ldm4t(vb, vsb + (vrow * SM_STRIDE + dcp * 16 + vcb) * 2);
                mma16816(Of[2*dcp],     P[jc][0], P[jc][1], P[jc][2], P[jc][3], vb[0], vb[1]);
                mma16816(Of[2*dcp + 1], P[jc][0], P[jc][1], P[jc][2], P[jc][3], vb[2], vb[3]);
            }
        }

        if (it + 1 < 64) {
            asm volatile("cp.async.wait_group 0;\n");
            __syncthreads();
        }
    }

    float inv0 = 1.0f / lrow0, inv1 = 1.0f / lrow1;
    int m = m0 + (w << 4) + gid;
    #pragma unroll
    for (int dc = 0; dc < 8; dc++) {
        int d0 = dc * 8 + tig * 2;
        g_O[(b * 64 + d0)     * NDS + m]     = Of[dc][0] * inv0;
        g_O[(b * 64 + d0 + 1) * NDS + m]     = Of[dc][1] * inv0;
        g_O[(b * 64 + d0)     * NDS + m + 8] = Of[dc][2] * inv1;
        g_O[(b * 64 + d0 + 1) * NDS + m + 8] = Of[dc][3] * inv1;
    }
}

// ============================================================================
// K5: convout — full-res conv0 on tensor cores (f16 hi/lo 3-pass) fused with
// out = relu(conv+bias) + tg*up4(O), plus ef_up = up4(ef_d).
// ============================================================================
#define CO_OFF_WH  0
#define CO_OFF_WL  25600
#define CO_OFF_ACT 51200
#define CO_ACT_BUF 16896
#define CONVOUT_SMEM (51200 + 2 * 17408)

__global__ __launch_bounds__(256, 2) void convout_kernel(
    const float* __restrict__ x1, const float* __restrict__ x2,
    const float* __restrict__ w,  const float* __restrict__ bias,
    const float* __restrict__ gamma, float* __restrict__ out)
{
    extern __shared__ char smc[];
    __half* WH = (__half*)(smc + CO_OFF_WH);
    __half* WL = (__half*)(smc + CO_OFF_WL);
    unsigned smu = (unsigned)__cvta_generic_to_shared(smc);

    int t = threadIdx.x;
    int lane = t & 31, wp = t >> 5;
    int ln15 = lane & 15, hb8 = (lane >> 4) * 8;
    int y = blockIdx.x, b = blockIdx.y;
    int p0 = y << 8;
    int ndbase = (y >> 2) << 6;

    for (int i = t; i < 12288; i += 256) {
        int o = i / 192, c = i - o * 192;
        float v = w[i];
        __half h = __float2half_rn(v);
        WH[o * 200 + c] = h;
        WL[o * 200 + c] = __float2half_rn(v - __half2float(h));
    }

    int r = t >> 4, col0 = (t & 15) << 4;
    float f[16];
    {
        const float* s = x1 + (size_t)(b * 128 + r) * HW + p0 + col0;
        #pragma unroll
        for (int j = 0; j < 4; j++) *(float4*)&f[4*j] = *(const float4*)(s + 4*j);
        unsigned H[8], L[8];
        #pragma unroll
        for (int j = 0; j < 8; j++) {
            __half h0 = __float2half_rn(f[2*j]), h1 = __float2half_rn(f[2*j+1]);
            H[j] = hpack(h0, h1);
            L[j] = hpack(__float2half_rn(f[2*j]   - __half2float(h0)),
                         __float2half_rn(f[2*j+1] - __half2float(h1)));
        }
        __half* AH = (__half*)(smc + CO_OFF_ACT);
        __half* AL = AH + 4224;
        *(uint4*)&AH[r * 264 + col0]     = make_uint4(H[0], H[1], H[2], H[3]);
        *(uint4*)&AH[r * 264 + col0 + 8] = make_uint4(H[4], H[5], H[6], H[7]);
        *(uint4*)&AL[r * 264 + col0]     = make_uint4(L[0], L[1], L[2], L[3]);
        *(uint4*)&AL[r * 264 + col0 + 8] = make_uint4(L[4], L[5], L[6], L[7]);
    }
    __syncthreads();

    float acc[4][4][4];
    #pragma unroll
    for (int mt = 0; mt < 4; mt++)
        #pragma unroll
        for (int nb = 0; nb < 4; nb++)
            #pragma unroll
            for (int q = 0; q < 4; q++) acc[mt][nb][q] = 0.0f;

    unsigned whB = smu + CO_OFF_WH + (ln15 * 200 + hb8) * 2;
    unsigned wlB = smu + CO_OFF_WL + (ln15 * 200 + hb8) * 2;

    #pragma unroll 1
    for (int ks = 0; ks < 12; ks++) {
        if (ks < 11) {
            int c = (ks + 1) * 16 + r;
            const float* s = (c < 128) ? x1 + (size_t)(b * 128 + c) * HW
                                       : x2 + (size_t)(b * 64 + c - 128) * HW;
            s += p0 + col0;
            #pragma unroll
            for (int j = 0; j < 4; j++) *(float4*)&f[4*j] = *(const float4*)(s + 4*j);
        }

        int bf = ks & 1;
        unsigned actH = smu + CO_OFF_ACT + bf * CO_ACT_BUF +
                        (ln15 * 264 + wp * 32 + hb8) * 2;
        unsigned actL = actH + 4224 * 2;

        unsigned A[4][4], Bh[8], Bl[8];
        ldm4t(Bh,     actH);
        ldm4t(Bh + 4, actH + 32);
        ldm4t(Bl,     actL);
        ldm4t(Bl + 4, actL + 32);
        #pragma unroll
        for (int mt = 0; mt < 4; mt++)
            ldm4(A[mt], whB + mt * 6400 + ks * 32);
        #pragma unroll
        for (int mt = 0; mt < 4; mt++) {
            mma16816(acc[mt][0], A[mt][0], A[mt][1], A[mt][2], A[mt][3], Bh[0], Bh[1]);
            mma16816(acc[mt][1], A[mt][0], A[mt][1], A[mt][2], A[mt][3], Bh[2], Bh[3]);
            mma16816(acc[mt][2], A[mt][0], A[mt][1], A[mt][2], A[mt][3], Bh[4], Bh[5]);
            mma16816(acc[mt][3], A[mt][0], A[mt][1], A[mt][2], A[mt][3], Bh[6], Bh[7]);
            mma16816(acc[mt][0], A[mt][0], A[mt][1], A[mt][2], A[mt][3], Bl[0], Bl[1]);
            mma16816(acc[mt][1], A[mt][0], A[mt][1], A[mt][2], A[mt][3], Bl[2], Bl[3]);
            mma16816(acc[mt][2], A[mt][0], A[mt][1], A[mt][2], A[mt][3], Bl[4], Bl[5]);
            mma16816(acc[mt][3], A[mt][0], A[mt][1], A[mt][2], A[mt][3], Bl[6], Bl[7]);
        }
        #pragma unroll
        for (int mt = 0; mt < 4; mt++)
            ldm4(A[mt], wlB + mt * 6400 + ks * 32);
        #pragma unroll
        for (int mt = 0; mt < 4; mt++) {
            mma16816(acc[mt][0], A[mt][0], A[mt][1], A[mt][2], A[mt][3], Bh[0], Bh[1]);
            mma16816(acc[mt][1], A[mt][0], A[mt][1], A[mt][2], A[mt][3], Bh[2], Bh[3]);
            mma16816(acc[mt][2], A[mt][0], A[mt][1], A[mt][2], A[mt][3], Bh[4], Bh[5]);
            mma16816(acc[mt][3], A[mt][0], A[mt][1], A[mt][2], A[mt][3], Bh[6], Bh[7]);
        }

        if (ks < 11) {
            unsigned H[8], L[8];
            #pragma unroll
            for (int j = 0; j < 8; j++) {
                __half h0 = __float2half_rn(f[2*j]), h1 = __float2half_rn(f[2*j+1]);
                H[j] = hpack(h0, h1);
                L[j] = hpack(__float2half_rn(f[2*j]   - __half2float(h0)),
                             __float2half_rn(f[2*j+1] - __half2float(h1)));
            }
            __half* AH = (__half*)(smc + CO_OFF_ACT + (bf ^ 1) * CO_ACT_BUF);
            __half* AL = AH + 4224;
            *(uint4*)&AH[r * 264 + col0]     = make_uint4(H[0], H[1], H[2], H[3]);
            *(uint4*)&AH[r * 264 + col0 + 8] = make_uint4(H[4], H[5], H[6], H[7]);
            *(uint4*)&AL[r * 264 + col0]     = make_uint4(L[0], L[1], L[2], L[3]);
            *(uint4*)&AL[r * 264 + col0 + 8] = make_uint4(L[4], L[5], L[6], L[7]);
            __syncthreads();
        }
    }

    // prefetch epilogue tiles to registers before overlaying smem
    float ov[16], ev[16];
    {
        int o = t >> 2, c0 = (t & 3) << 4;
        const float* po = g_O   + (size_t)(b * 64 + o) * NDS + ndbase + c0;
        const float* pe = g_efd + (size_t)(b * 64 + o) * NDS + ndbase + c0;
        #pragma unroll
        for (int j = 0; j < 4; j++) {
            *(float4*)&ov[4*j] = *(const float4*)(po + 4*j);
            *(float4*)&ev[4*j] = *(const float4*)(pe + 4*j);
        }
    }
    __syncthreads();

    float* OS = (float*)(smc + CO_OFF_ACT);
    float* ES = OS + 64 * 68;
    {
        int o = t >> 2, c0 = (t & 3) << 4;
        #pragma unroll
        for (int j = 0; j < 4; j++) {
            *(float4*)&OS[o * 68 + c0 + 4*j] = *(const float4*)&ov[4*j];
            *(float4*)&ES[o * 68 + c0 + 4*j] = *(const float4*)&ev[4*j];
        }
    }
    __syncthreads();

    float tg = THITA_F * __ldg(gamma);
    int g = lane >> 2, tig = lane & 3;
    #pragma unroll
    for (int mt = 0; mt < 4; mt++) {
        int o = mt * 16 + g;
        float bb0 = __ldg(&bias[o]), bb1 = __ldg(&bias[o + 8]);
        #pragma unroll
        for (int nb = 0; nb < 4; nb++) {
            int px = wp * 32 + nb * 8 + tig * 2;
            int ndc = px >> 2;
            float a0 = tg * OS[o * 68 + ndc];
            float a1 = tg * OS[(o + 8) * 68 + ndc];
            float2 r0 = make_float2(fmaxf(acc[mt][nb][0] + bb0, 0.0f) + a0,
                                    fmaxf(acc[mt][nb][1] + bb0, 0.0f) + a0);
            float2 r1 = make_float2(fmaxf(acc[mt][nb][2] + bb1, 0.0f) + a1,
                                    fmaxf(acc[mt][nb][3] + bb1, 0.0f) + a1);
            *(float2*)(out + (size_t)(b * 64 + o)     * HW + p0 + px) = r0;
            *(float2*)(out + (size_t)(b * 64 + o + 8) * HW + p0 + px) = r1;
        }
    }

    int xq = t & 63;
    #pragma unroll
    for (int rep = 0; rep < 16; rep++) {
        int o = rep * 4 + (t >> 6);
        float v = ES[o * 68 + xq];
        *(float4*)(out + OUT2OFF + (size_t)(b * 64 + o) * HW + p0 + (xq << 2)) =
            make_float4(v, v, v, v);
    }
}

// ============================================================================
extern "C" void kernel_launch(void* const* d_in, const int* in_sizes, int n_in,
                              void* d_out, int out_size)
{
    const float* x1    = (const float*)d_in[0];
    const float* x2    = (const float*)d_in[1];
    const float* ev    = (const float*)d_in[2];
    const float* xw0   = (const float*)d_in[3];
    const float* xb0   = (const float*)d_in[4];
    const float* xw1   = (const float*)d_in[5];
    const float* xb1   = (const float*)d_in[6];
    const float* ew0   = (const float*)d_in[7];
    const float* eb0   = (const float*)d_in[8];
    const float* ew1   = (const float*)d_in[9];
    const float* eb1   = (const float*)d_in[10];
    const float* qw    = (const float*)d_in[11];
    const float* qb    = (const float*)d_in[12];
    const float* kw    = (const float*)d_in[13];
    const float* kb    = (const float*)d_in[14];
    const float* vw    = (const float*)d_in[15];
    const float* vb    = (const float*)d_in[16];
    const float* gamma = (const float*)d_in[17];
    float* out = (float*)d_out;

    cudaFuncSetAttribute(conv0ds_kernel,
                         cudaFuncAttributeMaxDynamicSharedMemorySize, C0DS_SMEM);
    cudaFuncSetAttribute(ef_kernel,
                         cudaFuncAttributeMaxDynamicSharedMemorySize, EF_SMEM);
    cudaFuncSetAttribute(qkv_kernel,
                         cudaFuncAttributeMaxDynamicSharedMemorySize, QKV_SMEM);
    cudaFuncSetAttribute(attn_kernel,
                         cudaFuncAttributeMaxDynamicSharedMemorySize, ATTN_SMEM);
    cudaFuncSetAttribute(convout_kernel,
                         cudaFuncAttributeMaxDynamicSharedMemorySize, CONVOUT_SMEM);

    conv0ds_kernel<<<dim3(NDS / 64, BATCH), 256, C0DS_SMEM>>>(x1, x2, xw0, xb0);
    ef_kernel<<<dim3(NDS / 64, BATCH), 256, EF_SMEM>>>(ev, ew0, eb0, ew1, eb1);
    qkv_kernel<<<dim3(NDS / 64, BATCH), 256, QKV_SMEM>>>(xw1, xb1, qw, qb, kw, kb, vw, vb);
    attn_kernel<<<dim3(NDS / 64, BATCH), 128, ATTN_SMEM>>>();
    convout_kernel<<<dim3(256, BATCH), 256, CONVOUT_SMEM>>>(x1, x2, xw0, xb0, gamma, out);
}